// round 13
// baseline (speedup 1.0000x reference)
#include <cuda_runtime.h>
#include <cstdint>
#include <math.h>

// ---------------------------------------------------------------------------
// MultiHeadAttention, tf32 mma.sync GEMMs, cp.async 2-stage pipelines,
// ldmatrix fragment loads (single-buffered), fused softmax, fused QKV
// (v stored transposed). 3 CTAs/SM (12 warps/SM) for latency hiding.
// CTA 128x128x32, 4 warps (2x2 of 64x64 warp tiles).
// d_out = y [S,F] then attn [8,S,S] (fp32). S=4096, F=H=1024, dk=128.
// ---------------------------------------------------------------------------

#define SMAX 4096
#define HMAX 1024
#define NHEAD 8

__device__ float g_qkv[3 * SMAX * HMAX];     // q | k | (v unused plane)
__device__ float g_vt[HMAX * SMAX];          // v transposed [H][S]
__device__ float g_y[SMAX * HMAX];
__device__ float g_rs[NHEAD * SMAX];         // raw row sums of exp

__device__ __forceinline__ unsigned tf32u(unsigned x) {
    unsigned r;
    asm("cvt.rna.tf32.f32 %0, %1;" : "=r"(r) : "f"(__uint_as_float(x)));
    return r;
}
__device__ __forceinline__ float tf32f(float x) {
    unsigned r;
    asm("cvt.rna.tf32.f32 %0, %1;" : "=r"(r) : "f"(x));
    return __uint_as_float(r);
}
__device__ __forceinline__ void mma_tf32(float* c, const unsigned* a, const unsigned* b) {
    asm volatile(
        "mma.sync.aligned.m16n8k8.row.col.f32.tf32.tf32.f32 "
        "{%0,%1,%2,%3}, {%4,%5,%6,%7}, {%8,%9}, {%0,%1,%2,%3};"
        : "+f"(c[0]), "+f"(c[1]), "+f"(c[2]), "+f"(c[3])
        : "r"(a[0]), "r"(a[1]), "r"(a[2]), "r"(a[3]), "r"(b[0]), "r"(b[1]));
}
__device__ __forceinline__ void ldsm4(unsigned* r, uint32_t a) {
    asm volatile("ldmatrix.sync.aligned.m8n8.x4.shared.b16 {%0,%1,%2,%3}, [%4];"
        : "=r"(r[0]), "=r"(r[1]), "=r"(r[2]), "=r"(r[3]) : "r"(a));
}
__device__ __forceinline__ uint32_t smem_u32(const void* p) {
    uint32_t a;
    asm("{ .reg .u64 t; cvta.to.shared.u64 t, %1; cvt.u32.u64 %0, t; }" : "=r"(a) : "l"(p));
    return a;
}
__device__ __forceinline__ void cp16(uint32_t s, const void* g) {
    asm volatile("cp.async.cg.shared.global [%0], [%1], 16;" :: "r"(s), "l"(g));
}
#define CP_COMMIT() asm volatile("cp.async.commit_group;")
#define CP_WAIT0()  asm volatile("cp.async.wait_group 0;")

// Tile config: CTA 128(M) x 128(N) x 32(K), 4 warps (2m x 2n), warp tile 64x64.
#define MT  128
#define NT  128
#define BK  32
#define STAGES 2
#define NTHREADS 128
#define AS_STRIDE 36      // floats; [m][k] and TB [n][k]
#define BS_STRIDE 136     // NN layout [k][n]
#define A_BYTES  (128 * AS_STRIDE * 4)           // 18432
#define B_BYTES  (128 * AS_STRIDE * 4)           // 18432 (covers NN 17408 too)
#define STAGE_BYTES (A_BYTES + B_BYTES)          // 36864
#define SMEM_DYN (STAGES * STAGE_BYTES)          // 73728  (x3 CTAs = 221184)

// ---------------------------------------------------------------------------
// TB=false: C = alpha * A[M,K] @ B[K,N]   (B row-major; Bs [k][n] stride 136)
// TB=true : C = alpha * A[M,K] @ B[N,K]^T (B K-major;   Bs [n][k] stride 36)
// EXPE : epilogue C = exp(alpha*acc) fp32, atomicAdd fp32 row sums into rs
// NORM : A = raw exp values E via cp.async; each landed tile is re-read from
//        smem, scaled by 1/rs, written to Aw (final attn). Epilogue /rs.
// CVA/CVB : cvt.rna.tf32 on A/B fragments
// ROUND : round plain epilogue output to tf32 (when C feeds another GEMM)
// QKV3 : blockIdx.x = (bsel << 3) | n-tile; bsel 2 (v) stores transposed
//        into Aw as [H][S]; CTAs with blockIdx.x==0 zero rs.
// ---------------------------------------------------------------------------
template <bool TB, bool EXPE, bool NORM, bool CVA, bool CVB, bool ROUND, bool QKV3>
__global__ void __launch_bounds__(NTHREADS, 3) gemm_mha(
    const float* __restrict__ A, const float* __restrict__ B0,
    const float* __restrict__ B1, const float* __restrict__ B2,
    float* __restrict__ C, float* __restrict__ Aw, float* __restrict__ rs,
    int K, int lda, int ldb, int ldc,
    long long sA, long long sB, long long sC, float alpha, int S)
{
    extern __shared__ char smem[];
    const uint32_t sbase = smem_u32(smem);
    const int tid = threadIdx.x;
    const int lane = tid & 31;
    const int warp = tid >> 5;
    const int lg = lane >> 2;          // 0..7
    const int l4 = lane & 3;           // 0..3
    const int wm = (warp & 1) * 64;    // 2 m-warps
    const int wn = (warp >> 1) * 64;   // 2 n-warps

    // ldmatrix lane offsets (bytes, relative to tile base)
    const int lgp = lane >> 3, ri = lane & 7;
    const uint32_t aoff = (uint32_t)((wm + ((lgp & 1) << 3) + ri) * (AS_STRIDE * 4)
                                     + ((lgp >> 1) << 4));
    const uint32_t boff = (uint32_t)((wn + ((lgp >> 1) << 3) + ri) * (AS_STRIDE * 4)
                                     + ((lgp & 1) << 4));   // TB layout only

    const int m0 = blockIdx.y * MT;
    int n0;
    const float* B;
    float* Cm;
    bool trc = false;
    if (QKV3) {
        const int bsel = blockIdx.x >> 3;
        n0 = (blockIdx.x & 7) * NT;
        B = (bsel == 0) ? B0 : ((bsel == 1) ? B1 : B2);
        Cm = C + (long long)bsel * sC;
        trc = (bsel == 2);
        if (blockIdx.x == 0) {
            float4 z = make_float4(0.f, 0.f, 0.f, 0.f);
            float* p = rs + blockIdx.y * (NHEAD * S / 32) + tid * 8;
            *(float4*)p = z;
            *(float4*)(p + 4) = z;
        }
    } else {
        n0 = blockIdx.x * NT;
        B = B0;
        Cm = C + (long long)blockIdx.z * sC;
    }

    const float* Ab = A + (long long)blockIdx.z * sA + (long long)m0 * lda;
    float* Awb = NORM ? (Aw + (long long)blockIdx.z * sA + (long long)m0 * lda) : nullptr;
    const float* Bb;
    if (TB) Bb = B + (long long)blockIdx.z * sB + (long long)n0 * ldb;
    else    Bb = B + (long long)blockIdx.z * sB + n0;
    float* Cb = Cm + (long long)m0 * ldc + n0;

    // loader mappings (128 threads)
    const int a_r = tid >> 3;            // 0..15 (+16i, i=0..7)
    const int a_c = (tid & 7) * 4;       // float col base (16B chunk)
    const int bn_k = tid >> 5;           // 0..3 (+4i, i=0..7)
    const int bn_c = (tid & 31) * 4;

    float inv[8];
    if (NORM) {
#pragma unroll
        for (int i = 0; i < 8; i++)
            inv[i] = 1.0f / rs[blockIdx.z * S + m0 + a_r + 16 * i];
    }

    float acc[4][8][4];
#pragma unroll
    for (int mt = 0; mt < 4; mt++)
#pragma unroll
        for (int nt = 0; nt < 8; nt++)
#pragma unroll
            for (int i = 0; i < 4; i++) acc[mt][nt][i] = 0.0f;

    const int ktiles = K / BK;

    auto issueA = [&](int st, int kt) {
        const uint32_t as = sbase + st * STAGE_BYTES;
        const float* p = Ab + (long long)a_r * lda + kt * BK + a_c;
#pragma unroll
        for (int i = 0; i < 8; i++)
            cp16(as + (uint32_t)(((a_r + 16 * i) * AS_STRIDE + a_c) * 4),
                 p + (long long)(16 * i) * lda);
    };
    auto issueB = [&](int st, int kt) {
        const uint32_t bs = sbase + st * STAGE_BYTES + A_BYTES;
        if (TB) {
            const float* p = Bb + (long long)a_r * ldb + kt * BK + a_c;
#pragma unroll
            for (int i = 0; i < 8; i++)
                cp16(bs + (uint32_t)(((a_r + 16 * i) * AS_STRIDE + a_c) * 4),
                     p + (long long)(16 * i) * ldb);
        } else {
            const float* p = Bb + (long long)(kt * BK + bn_k) * ldb + bn_c;
#pragma unroll
            for (int i = 0; i < 8; i++)
                cp16(bs + (uint32_t)(((bn_k + 4 * i) * BS_STRIDE + bn_c) * 4),
                     p + (long long)(4 * i) * ldb);
        }
    };
    // NORM: read raw E tile from smem, scale by 1/rs, write final attn to gmem
    auto wrNorm = [&](int st, int kt) {
        const float* As = (const float*)(smem + st * STAGE_BYTES);
#pragma unroll
        for (int i = 0; i < 8; i++) {
            float4 v = *(const float4*)&As[(a_r + 16 * i) * AS_STRIDE + a_c];
            v.x *= inv[i]; v.y *= inv[i]; v.z *= inv[i]; v.w *= inv[i];
            *(float4*)(Awb + (long long)(a_r + 16 * i) * lda + kt * BK + a_c) = v;
        }
    };

    // ---- prologue: fill stage 0 ----
    issueA(0, 0);
    issueB(0, 0);
    CP_COMMIT();

    for (int kt = 0; kt < ktiles; kt++) {
        const int cur = kt & 1;
        // current tile's cp.async group is the only (or oldest) pending one
        CP_WAIT0();
        __syncthreads();   // also: all warps done reading buffer cur^1 (kt-1)

        if (kt + 1 < ktiles) {
            issueA(cur ^ 1, kt + 1);
            issueB(cur ^ 1, kt + 1);
            CP_COMMIT();
        }

        if (NORM) wrNorm(cur, kt);

        const uint32_t as_s = sbase + cur * STAGE_BYTES;
        const uint32_t bs_s = as_s + A_BYTES;
        const float* Bs = (const float*)(smem + cur * STAGE_BYTES + A_BYTES);

        // single-buffered fragments (register economy -> 3 CTAs/SM)
#pragma unroll
        for (int ks = 0; ks < 4; ks++) {
            unsigned af[4][4], bf[8][2];
#pragma unroll
            for (int mt = 0; mt < 4; mt++) {
                unsigned r[4];
                ldsm4(r, as_s + aoff + (uint32_t)(mt * 16 * AS_STRIDE * 4 + ks * 32));
                af[mt][0] = CVA ? tf32u(r[0]) : r[0];
                af[mt][1] = CVA ? tf32u(r[1]) : r[1];
                af[mt][2] = CVA ? tf32u(r[2]) : r[2];
                af[mt][3] = CVA ? tf32u(r[3]) : r[3];
            }
            if (TB) {
#pragma unroll
                for (int np = 0; np < 4; np++) {
                    unsigned r[4];
                    ldsm4(r, bs_s + boff + (uint32_t)(np * 16 * AS_STRIDE * 4 + ks * 32));
                    bf[2 * np][0]     = CVB ? tf32u(r[0]) : r[0];
                    bf[2 * np][1]     = CVB ? tf32u(r[1]) : r[1];
                    bf[2 * np + 1][0] = CVB ? tf32u(r[2]) : r[2];
                    bf[2 * np + 1][1] = CVB ? tf32u(r[3]) : r[3];
                }
            } else {
                const int k = ks * 8;
#pragma unroll
                for (int nt = 0; nt < 8; nt++) {
                    const int c = wn + nt * 8 + lg;
                    unsigned v0 = __float_as_uint(Bs[(k + l4) * BS_STRIDE + c]);
                    unsigned v1 = __float_as_uint(Bs[(k + l4 + 4) * BS_STRIDE + c]);
                    bf[nt][0] = CVB ? tf32u(v0) : v0;
                    bf[nt][1] = CVB ? tf32u(v1) : v1;
                }
            }
#pragma unroll
            for (int mt = 0; mt < 4; mt++)
#pragma unroll
                for (int nt = 0; nt < 8; nt++)
                    mma_tf32(acc[mt][nt], af[mt], bf[nt]);
        }
    }

    // ---- epilogue ----
    if (EXPE) {
        float ps[4][2];
#pragma unroll
        for (int mt = 0; mt < 4; mt++) { ps[mt][0] = 0.0f; ps[mt][1] = 0.0f; }
#pragma unroll
        for (int mt = 0; mt < 4; mt++) {
            const int r = wm + mt * 16 + lg;
#pragma unroll
            for (int nt = 0; nt < 8; nt++) {
                const int c = wn + nt * 8 + 2 * l4;
                float e0 = __expf(acc[mt][nt][0] * alpha);
                float e1 = __expf(acc[mt][nt][1] * alpha);
                float e2 = __expf(acc[mt][nt][2] * alpha);
                float e3 = __expf(acc[mt][nt][3] * alpha);
                *(float2*)(Cb + (long long)r * ldc + c) = make_float2(e0, e1);
                *(float2*)(Cb + (long long)(r + 8) * ldc + c) = make_float2(e2, e3);
                ps[mt][0] += e0 + e1;
                ps[mt][1] += e2 + e3;
            }
        }
#pragma unroll
        for (int mt = 0; mt < 4; mt++) {
#pragma unroll
            for (int h = 0; h < 2; h++) {
                float v = ps[mt][h];
                v += __shfl_xor_sync(0xffffffffu, v, 1);
                v += __shfl_xor_sync(0xffffffffu, v, 2);
                if (l4 == 0)
                    atomicAdd(&rs[blockIdx.z * S + m0 + wm + mt * 16 + lg + h * 8], v);
            }
        }
    } else {
#pragma unroll
        for (int mt = 0; mt < 4; mt++) {
            const int r = wm + mt * 16 + lg;
            float s0 = alpha, s1 = alpha;
            if (NORM) {
                s0 = 1.0f / rs[blockIdx.z * S + m0 + r];
                s1 = 1.0f / rs[blockIdx.z * S + m0 + r + 8];
            }
#pragma unroll
            for (int nt = 0; nt < 8; nt++) {
                const int c = wn + nt * 8 + 2 * l4;
                float o0 = acc[mt][nt][0] * s0, o1 = acc[mt][nt][1] * s0;
                float o2 = acc[mt][nt][2] * s1, o3 = acc[mt][nt][3] * s1;
                if (ROUND) {
                    o0 = tf32f(o0); o1 = tf32f(o1);
                    o2 = tf32f(o2); o3 = tf32f(o3);
                }
                if (QKV3 && trc) {
                    const long long gm = m0 + r;
                    const int gc = n0 + c;
                    Aw[(long long)gc * S + gm]           = o0;
                    Aw[(long long)(gc + 1) * S + gm]     = o1;
                    Aw[(long long)gc * S + gm + 8]       = o2;
                    Aw[(long long)(gc + 1) * S + gm + 8] = o3;
                } else {
                    *(float2*)(Cb + (long long)r * ldc + c) = make_float2(o0, o1);
                    *(float2*)(Cb + (long long)(r + 8) * ldc + c) = make_float2(o2, o3);
                }
            }
        }
    }
}

extern "C" void kernel_launch(void* const* d_in, const int* in_sizes, int n_in,
                              void* d_out, int out_size)
{
    const float* x  = (const float*)d_in[0];
    const float* Wq = (const float*)d_in[1];
    const float* Wk = (const float*)d_in[2];
    const float* Wv = (const float*)d_in[3];
    const float* Wo = (const float*)d_in[4];

    const int F  = 1024;
    const int H  = 1024;
    const int NH = NHEAD;
    const int DK = H / NH;                 // 128
    const int S  = in_sizes[0] / F;        // 4096

    float* y_out    = (float*)d_out;
    float* attn_out = y_out + (long long)S * H;

    float *qkv, *vt, *y, *rs;
    cudaGetSymbolAddress((void**)&qkv, g_qkv);
    cudaGetSymbolAddress((void**)&vt, g_vt);
    cudaGetSymbolAddress((void**)&y, g_y);
    cudaGetSymbolAddress((void**)&rs, g_rs);
    float* q = qkv;
    float* k = qkv + (long long)S * H;

    // template args: TB, EXPE, NORM, CVA, CVB, ROUND, QKV3
    auto kQKV  = gemm_mha<false, false, false, true,  true,  true,  true >;
    auto kQKT  = gemm_mha<true,  true,  false, false, false, false, false>;
    auto kAV   = gemm_mha<true,  false, true,  true,  false, true,  false>;
    auto kPROJ = gemm_mha<false, false, false, false, true,  false, false>;

    cudaFuncSetAttribute(kQKV,  cudaFuncAttributeMaxDynamicSharedMemorySize, SMEM_DYN);
    cudaFuncSetAttribute(kQKT,  cudaFuncAttributeMaxDynamicSharedMemorySize, SMEM_DYN);
    cudaFuncSetAttribute(kAV,   cudaFuncAttributeMaxDynamicSharedMemorySize, SMEM_DYN);
    cudaFuncSetAttribute(kPROJ, cudaFuncAttributeMaxDynamicSharedMemorySize, SMEM_DYN);

    const dim3 blk(NTHREADS);
    const float inv_sqrt_dk = 0.08838834764831845f;  // 1/sqrt(128)

    // 1) fused Q/K/V projections (+rs zeroing); v written transposed to g_vt
    dim3 g1(3 * (H / NT), S / MT, 1);
    kQKV<<<g1, blk, SMEM_DYN>>>(x, Wq, Wk, Wv, qkv, vt, rs,
                                F, F, H, H, 0, 0, (long long)S * H, 1.0f, S);

    // 2) logits -> exp(Q K^T / sqrt(dk)) fp32 into attn region + raw row sums
    dim3 g2(S / NT, S / MT, NH);
    kQKT<<<g2, blk, SMEM_DYN>>>(q, k, nullptr, nullptr, attn_out, nullptr, rs,
                                DK, H, H, S,
                                (long long)DK, (long long)DK, (long long)S * S,
                                inv_sqrt_dk, S);

    // 3) AV (TB, all-ldsm): Y = (E @ Vt^T)/rs; writes normalized attn from smem
    dim3 g3(DK / NT, S / MT, NH);
    kAV<<<g3, blk, SMEM_DYN>>>(attn_out, vt, nullptr, nullptr, y, attn_out, rs,
                               S, S, S, H,
                               (long long)S * S, (long long)DK * S, (long long)DK,
                               1.0f, S);

    // 4) output projection: y_out = Y @ Wo (fp32 out)
    dim3 g4(F / NT, S / MT, 1);
    kPROJ<<<g4, blk, SMEM_DYN>>>(y, Wo, nullptr, nullptr, y_out, nullptr, rs,
                                 H, H, F, F, 0, 0, 0, 1.0f, S);
}

// round 14
// speedup vs baseline: 1.1291x; 1.1291x over previous
#include <cuda_runtime.h>
#include <cstdint>
#include <math.h>

// ---------------------------------------------------------------------------
// MultiHeadAttention, tf32 mma.sync GEMMs, cp.async 3-stage pipelines,
// ldmatrix fragment loads (single-buffered everywhere), fused softmax,
// fused QKV (v stored transposed). CTA 128x128x32, 4 warps, 2 CTAs/SM.
// d_out = y [S,F] then attn [8,S,S] (fp32). S=4096, F=H=1024, dk=128.
// ---------------------------------------------------------------------------

#define SMAX 4096
#define HMAX 1024
#define NHEAD 8

__device__ float g_qkv[3 * SMAX * HMAX];     // q | k | (v unused plane)
__device__ float g_vt[HMAX * SMAX];          // v transposed [H][S]
__device__ float g_y[SMAX * HMAX];
__device__ float g_rs[NHEAD * SMAX];         // raw row sums of exp

__device__ __forceinline__ unsigned tf32u(unsigned x) {
    unsigned r;
    asm("cvt.rna.tf32.f32 %0, %1;" : "=r"(r) : "f"(__uint_as_float(x)));
    return r;
}
__device__ __forceinline__ float tf32f(float x) {
    unsigned r;
    asm("cvt.rna.tf32.f32 %0, %1;" : "=r"(r) : "f"(x));
    return __uint_as_float(r);
}
__device__ __forceinline__ void mma_tf32(float* c, const unsigned* a, const unsigned* b) {
    asm volatile(
        "mma.sync.aligned.m16n8k8.row.col.f32.tf32.tf32.f32 "
        "{%0,%1,%2,%3}, {%4,%5,%6,%7}, {%8,%9}, {%0,%1,%2,%3};"
        : "+f"(c[0]), "+f"(c[1]), "+f"(c[2]), "+f"(c[3])
        : "r"(a[0]), "r"(a[1]), "r"(a[2]), "r"(a[3]), "r"(b[0]), "r"(b[1]));
}
__device__ __forceinline__ void ldsm4(unsigned* r, uint32_t a) {
    asm volatile("ldmatrix.sync.aligned.m8n8.x4.shared.b16 {%0,%1,%2,%3}, [%4];"
        : "=r"(r[0]), "=r"(r[1]), "=r"(r[2]), "=r"(r[3]) : "r"(a));
}
__device__ __forceinline__ uint32_t smem_u32(const void* p) {
    uint32_t a;
    asm("{ .reg .u64 t; cvta.to.shared.u64 t, %1; cvt.u32.u64 %0, t; }" : "=r"(a) : "l"(p));
    return a;
}
__device__ __forceinline__ void cp16(uint32_t s, const void* g) {
    asm volatile("cp.async.cg.shared.global [%0], [%1], 16;" :: "r"(s), "l"(g));
}
#define CP_COMMIT() asm volatile("cp.async.commit_group;")
#define CP_WAIT1()  asm volatile("cp.async.wait_group 1;")
#define CP_WAIT0()  asm volatile("cp.async.wait_group 0;")

// Tile config: CTA 128(M) x 128(N) x 32(K), 4 warps (2m x 2n), warp tile 64x64.
#define MT  128
#define NT  128
#define BK  32
#define STAGES 3
#define NTHREADS 128
#define AS_STRIDE 36      // floats; [m][k] and TB [n][k]
#define BS_STRIDE 136     // NN layout [k][n]
#define A_BYTES  (128 * AS_STRIDE * 4)           // 18432
#define B_BYTES  (128 * AS_STRIDE * 4)           // 18432 (covers NN 17408 too)
#define STAGE_BYTES (A_BYTES + B_BYTES)          // 36864
#define SMEM_DYN (STAGES * STAGE_BYTES)          // 110592  (x2 CTAs = 221184)

// ---------------------------------------------------------------------------
// TB=false: C = alpha * A[M,K] @ B[K,N]   (B row-major; Bs [k][n] stride 136)
// TB=true : C = alpha * A[M,K] @ B[N,K]^T (B K-major;   Bs [n][k] stride 36)
// EXPE : epilogue C = exp(alpha*acc) fp32, atomicAdd fp32 row sums into rs
// NORM : A = raw exp values E via cp.async; each landed tile is re-read from
//        smem, scaled by 1/rs, written to Aw (final attn). Epilogue /rs.
// CVA/CVB : cvt.rna.tf32 on A/B fragments
// ROUND : round plain epilogue output to tf32 (when C feeds another GEMM)
// QKV3 : blockIdx.x = (bsel << 3) | n-tile; bsel 2 (v) stores transposed
//        into Aw as [H][S]; CTAs with blockIdx.x==0 zero rs.
// ---------------------------------------------------------------------------
template <bool TB, bool EXPE, bool NORM, bool CVA, bool CVB, bool ROUND, bool QKV3>
__global__ void __launch_bounds__(NTHREADS, 2) gemm_mha(
    const float* __restrict__ A, const float* __restrict__ B0,
    const float* __restrict__ B1, const float* __restrict__ B2,
    float* __restrict__ C, float* __restrict__ Aw, float* __restrict__ rs,
    int K, int lda, int ldb, int ldc,
    long long sA, long long sB, long long sC, float alpha, int S)
{
    extern __shared__ char smem[];
    const uint32_t sbase = smem_u32(smem);
    const int tid = threadIdx.x;
    const int lane = tid & 31;
    const int warp = tid >> 5;
    const int lg = lane >> 2;          // 0..7
    const int l4 = lane & 3;           // 0..3
    const int wm = (warp & 1) * 64;    // 2 m-warps
    const int wn = (warp >> 1) * 64;   // 2 n-warps

    // ldmatrix lane offsets (bytes, relative to tile base)
    const int lgp = lane >> 3, ri = lane & 7;
    const uint32_t aoff = (uint32_t)((wm + ((lgp & 1) << 3) + ri) * (AS_STRIDE * 4)
                                     + ((lgp >> 1) << 4));
    const uint32_t boff = (uint32_t)((wn + ((lgp >> 1) << 3) + ri) * (AS_STRIDE * 4)
                                     + ((lgp & 1) << 4));   // TB layout only

    const int m0 = blockIdx.y * MT;
    int n0;
    const float* B;
    float* Cm;
    bool trc = false;
    if (QKV3) {
        const int bsel = blockIdx.x >> 3;
        n0 = (blockIdx.x & 7) * NT;
        B = (bsel == 0) ? B0 : ((bsel == 1) ? B1 : B2);
        Cm = C + (long long)bsel * sC;
        trc = (bsel == 2);
        if (blockIdx.x == 0) {
            float4 z = make_float4(0.f, 0.f, 0.f, 0.f);
            float* p = rs + blockIdx.y * (NHEAD * S / 32) + tid * 8;
            *(float4*)p = z;
            *(float4*)(p + 4) = z;
        }
    } else {
        n0 = blockIdx.x * NT;
        B = B0;
        Cm = C + (long long)blockIdx.z * sC;
    }

    const float* Ab = A + (long long)blockIdx.z * sA + (long long)m0 * lda;
    float* Awb = NORM ? (Aw + (long long)blockIdx.z * sA + (long long)m0 * lda) : nullptr;
    const float* Bb;
    if (TB) Bb = B + (long long)blockIdx.z * sB + (long long)n0 * ldb;
    else    Bb = B + (long long)blockIdx.z * sB + n0;
    float* Cb = Cm + (long long)m0 * ldc + n0;

    // loader mappings (128 threads)
    const int a_r = tid >> 3;            // 0..15 (+16i, i=0..7)
    const int a_c = (tid & 7) * 4;       // float col base (16B chunk)
    const int bn_k = tid >> 5;           // 0..3 (+4i, i=0..7)
    const int bn_c = (tid & 31) * 4;

    float inv[8];
    if (NORM) {
#pragma unroll
        for (int i = 0; i < 8; i++)
            inv[i] = 1.0f / rs[blockIdx.z * S + m0 + a_r + 16 * i];
    }

    float acc[4][8][4];
#pragma unroll
    for (int mt = 0; mt < 4; mt++)
#pragma unroll
        for (int nt = 0; nt < 8; nt++)
#pragma unroll
            for (int i = 0; i < 4; i++) acc[mt][nt][i] = 0.0f;

    const int ktiles = K / BK;

    auto issueA = [&](int st, int kt) {
        const uint32_t as = sbase + st * STAGE_BYTES;
        const float* p = Ab + (long long)a_r * lda + kt * BK + a_c;
#pragma unroll
        for (int i = 0; i < 8; i++)
            cp16(as + (uint32_t)(((a_r + 16 * i) * AS_STRIDE + a_c) * 4),
                 p + (long long)(16 * i) * lda);
    };
    auto issueB = [&](int st, int kt) {
        const uint32_t bs = sbase + st * STAGE_BYTES + A_BYTES;
        if (TB) {
            const float* p = Bb + (long long)a_r * ldb + kt * BK + a_c;
#pragma unroll
            for (int i = 0; i < 8; i++)
                cp16(bs + (uint32_t)(((a_r + 16 * i) * AS_STRIDE + a_c) * 4),
                     p + (long long)(16 * i) * ldb);
        } else {
            const float* p = Bb + (long long)(kt * BK + bn_k) * ldb + bn_c;
#pragma unroll
            for (int i = 0; i < 8; i++)
                cp16(bs + (uint32_t)(((bn_k + 4 * i) * BS_STRIDE + bn_c) * 4),
                     p + (long long)(4 * i) * ldb);
        }
    };
    // NORM: read raw E tile from smem, scale by 1/rs, write final attn to gmem
    auto wrNorm = [&](int st, int kt) {
        const float* As = (const float*)(smem + st * STAGE_BYTES);
#pragma unroll
        for (int i = 0; i < 8; i++) {
            float4 v = *(const float4*)&As[(a_r + 16 * i) * AS_STRIDE + a_c];
            v.x *= inv[i]; v.y *= inv[i]; v.z *= inv[i]; v.w *= inv[i];
            *(float4*)(Awb + (long long)(a_r + 16 * i) * lda + kt * BK + a_c) = v;
        }
    };

    // ---- prologue: fill stages 0,1 ----
#pragma unroll
    for (int s = 0; s < 2; s++) {
        issueA(s, s);
        issueB(s, s);
        CP_COMMIT();
    }

    for (int kt = 0; kt < ktiles; kt++) {
        const int cur = kt % STAGES;
        const bool has = (kt + 2 < ktiles);
        if (has) CP_WAIT1(); else CP_WAIT0();
        __syncthreads();

        const int nx = (kt + 2) % STAGES;
        if (has) {
            issueA(nx, kt + 2);
            issueB(nx, kt + 2);
            CP_COMMIT();
        }

        if (NORM) wrNorm(cur, kt);

        const uint32_t as_s = sbase + cur * STAGE_BYTES;
        const uint32_t bs_s = as_s + A_BYTES;
        const float* Bs = (const float*)(smem + cur * STAGE_BYTES + A_BYTES);

        // single-buffered fragments (register economy; R13-validated faster)
#pragma unroll
        for (int ks = 0; ks < 4; ks++) {
            unsigned af[4][4], bf[8][2];
#pragma unroll
            for (int mt = 0; mt < 4; mt++) {
                unsigned r[4];
                ldsm4(r, as_s + aoff + (uint32_t)(mt * 16 * AS_STRIDE * 4 + ks * 32));
                af[mt][0] = CVA ? tf32u(r[0]) : r[0];
                af[mt][1] = CVA ? tf32u(r[1]) : r[1];
                af[mt][2] = CVA ? tf32u(r[2]) : r[2];
                af[mt][3] = CVA ? tf32u(r[3]) : r[3];
            }
            if (TB) {
#pragma unroll
                for (int np = 0; np < 4; np++) {
                    unsigned r[4];
                    ldsm4(r, bs_s + boff + (uint32_t)(np * 16 * AS_STRIDE * 4 + ks * 32));
                    bf[2 * np][0]     = CVB ? tf32u(r[0]) : r[0];
                    bf[2 * np][1]     = CVB ? tf32u(r[1]) : r[1];
                    bf[2 * np + 1][0] = CVB ? tf32u(r[2]) : r[2];
                    bf[2 * np + 1][1] = CVB ? tf32u(r[3]) : r[3];
                }
            } else {
                const int k = ks * 8;
#pragma unroll
                for (int nt = 0; nt < 8; nt++) {
                    const int c = wn + nt * 8 + lg;
                    unsigned v0 = __float_as_uint(Bs[(k + l4) * BS_STRIDE + c]);
                    unsigned v1 = __float_as_uint(Bs[(k + l4 + 4) * BS_STRIDE + c]);
                    bf[nt][0] = CVB ? tf32u(v0) : v0;
                    bf[nt][1] = CVB ? tf32u(v1) : v1;
                }
            }
#pragma unroll
            for (int mt = 0; mt < 4; mt++)
#pragma unroll
                for (int nt = 0; nt < 8; nt++)
                    mma_tf32(acc[mt][nt], af[mt], bf[nt]);
        }
    }

    // ---- epilogue ----
    if (EXPE) {
        float ps[4][2];
#pragma unroll
        for (int mt = 0; mt < 4; mt++) { ps[mt][0] = 0.0f; ps[mt][1] = 0.0f; }
#pragma unroll
        for (int mt = 0; mt < 4; mt++) {
            const int r = wm + mt * 16 + lg;
#pragma unroll
            for (int nt = 0; nt < 8; nt++) {
                const int c = wn + nt * 8 + 2 * l4;
                float e0 = __expf(acc[mt][nt][0] * alpha);
                float e1 = __expf(acc[mt][nt][1] * alpha);
                float e2 = __expf(acc[mt][nt][2] * alpha);
                float e3 = __expf(acc[mt][nt][3] * alpha);
                *(float2*)(Cb + (long long)r * ldc + c) = make_float2(e0, e1);
                *(float2*)(Cb + (long long)(r + 8) * ldc + c) = make_float2(e2, e3);
                ps[mt][0] += e0 + e1;
                ps[mt][1] += e2 + e3;
            }
        }
#pragma unroll
        for (int mt = 0; mt < 4; mt++) {
#pragma unroll
            for (int h = 0; h < 2; h++) {
                float v = ps[mt][h];
                v += __shfl_xor_sync(0xffffffffu, v, 1);
                v += __shfl_xor_sync(0xffffffffu, v, 2);
                if (l4 == 0)
                    atomicAdd(&rs[blockIdx.z * S + m0 + wm + mt * 16 + lg + h * 8], v);
            }
        }
    } else {
#pragma unroll
        for (int mt = 0; mt < 4; mt++) {
            const int r = wm + mt * 16 + lg;
            float s0 = alpha, s1 = alpha;
            if (NORM) {
                s0 = 1.0f / rs[blockIdx.z * S + m0 + r];
                s1 = 1.0f / rs[blockIdx.z * S + m0 + r + 8];
            }
#pragma unroll
            for (int nt = 0; nt < 8; nt++) {
                const int c = wn + nt * 8 + 2 * l4;
                float o0 = acc[mt][nt][0] * s0, o1 = acc[mt][nt][1] * s0;
                float o2 = acc[mt][nt][2] * s1, o3 = acc[mt][nt][3] * s1;
                if (ROUND) {
                    o0 = tf32f(o0); o1 = tf32f(o1);
                    o2 = tf32f(o2); o3 = tf32f(o3);
                }
                if (QKV3 && trc) {
                    const long long gm = m0 + r;
                    const int gc = n0 + c;
                    Aw[(long long)gc * S + gm]           = o0;
                    Aw[(long long)(gc + 1) * S + gm]     = o1;
                    Aw[(long long)gc * S + gm + 8]       = o2;
                    Aw[(long long)(gc + 1) * S + gm + 8] = o3;
                } else {
                    *(float2*)(Cb + (long long)r * ldc + c) = make_float2(o0, o1);
                    *(float2*)(Cb + (long long)(r + 8) * ldc + c) = make_float2(o2, o3);
                }
            }
        }
    }
}

extern "C" void kernel_launch(void* const* d_in, const int* in_sizes, int n_in,
                              void* d_out, int out_size)
{
    const float* x  = (const float*)d_in[0];
    const float* Wq = (const float*)d_in[1];
    const float* Wk = (const float*)d_in[2];
    const float* Wv = (const float*)d_in[3];
    const float* Wo = (const float*)d_in[4];

    const int F  = 1024;
    const int H  = 1024;
    const int NH = NHEAD;
    const int DK = H / NH;                 // 128
    const int S  = in_sizes[0] / F;        // 4096

    float* y_out    = (float*)d_out;
    float* attn_out = y_out + (long long)S * H;

    float *qkv, *vt, *y, *rs;
    cudaGetSymbolAddress((void**)&qkv, g_qkv);
    cudaGetSymbolAddress((void**)&vt, g_vt);
    cudaGetSymbolAddress((void**)&y, g_y);
    cudaGetSymbolAddress((void**)&rs, g_rs);
    float* q = qkv;
    float* k = qkv + (long long)S * H;

    // template args: TB, EXPE, NORM, CVA, CVB, ROUND, QKV3
    auto kQKV  = gemm_mha<false, false, false, true,  true,  true,  true >;
    auto kQKT  = gemm_mha<true,  true,  false, false, false, false, false>;
    auto kAV   = gemm_mha<true,  false, true,  true,  false, true,  false>;
    auto kPROJ = gemm_mha<false, false, false, false, true,  false, false>;

    cudaFuncSetAttribute(kQKV,  cudaFuncAttributeMaxDynamicSharedMemorySize, SMEM_DYN);
    cudaFuncSetAttribute(kQKT,  cudaFuncAttributeMaxDynamicSharedMemorySize, SMEM_DYN);
    cudaFuncSetAttribute(kAV,   cudaFuncAttributeMaxDynamicSharedMemorySize, SMEM_DYN);
    cudaFuncSetAttribute(kPROJ, cudaFuncAttributeMaxDynamicSharedMemorySize, SMEM_DYN);

    const dim3 blk(NTHREADS);
    const float inv_sqrt_dk = 0.08838834764831845f;  // 1/sqrt(128)

    // 1) fused Q/K/V projections (+rs zeroing); v written transposed to g_vt
    dim3 g1(3 * (H / NT), S / MT, 1);
    kQKV<<<g1, blk, SMEM_DYN>>>(x, Wq, Wk, Wv, qkv, vt, rs,
                                F, F, H, H, 0, 0, (long long)S * H, 1.0f, S);

    // 2) logits -> exp(Q K^T / sqrt(dk)) fp32 into attn region + raw row sums
    dim3 g2(S / NT, S / MT, NH);
    kQKT<<<g2, blk, SMEM_DYN>>>(q, k, nullptr, nullptr, attn_out, nullptr, rs,
                                DK, H, H, S,
                                (long long)DK, (long long)DK, (long long)S * S,
                                inv_sqrt_dk, S);

    // 3) AV (TB, all-ldsm): Y = (E @ Vt^T)/rs; writes normalized attn from smem
    dim3 g3(DK / NT, S / MT, NH);
    kAV<<<g3, blk, SMEM_DYN>>>(attn_out, vt, nullptr, nullptr, y, attn_out, rs,
                               S, S, S, H,
                               (long long)S * S, (long long)DK * S, (long long)DK,
                               1.0f, S);

    // 4) output projection: y_out = Y @ Wo (fp32 out)
    dim3 g4(F / NT, S / MT, 1);
    kPROJ<<<g4, blk, SMEM_DYN>>>(y, Wo, nullptr, nullptr, y_out, nullptr, rs,
                                 H, H, F, F, 0, 0, 0, 1.0f, S);
}